// round 16
// baseline (speedup 1.0000x reference)
#include <cuda_runtime.h>
#include <cstdint>

#define BB 16
#define NN 25200
#define NCLS 80
#define PSTR 85
#define MAX_DET 300
#define M_TGT 50
#define CONF_THRES 0.8f
#define NMS_THRES 0.4f
#define NBINS 512
#define SLOTS 64         // per-bin capacity (E[cnt]≈9.4, 5-sigma < 30)
#define SURV_MAX 512     // S <= 300 + SLOTS
#define KW 10            // ceil(300/32)
#define KWPAD 12         // pad rows to 48B for uint4 loads
#define BPB 50           // blocks per batch (score)
#define APB 504          // anchors per block = NN/BPB
#define APW 63           // anchors per warp = APB/8
#define SCORE_THREADS 256

// ---- global scratch (zero-init at load; post_kernel re-zeros g_hist per call) ----
__device__ int                g_hist[BB][NBINS];
__device__ unsigned long long g_bin[BB][NBINS][SLOTS];

__device__ __forceinline__ int score_bin(float sc) {
    int b = (int)((sc - CONF_THRES) * (NBINS / 0.2f));
    if (b < 0) b = 0;
    if (b >= NBINS) b = NBINS - 1;
    return b;
}

// ============ Kernel A: obj-gated scan, pipelined candidates, bin-bucketed emit ============
// Exact gate: cls in [0,1) so maxcls < 1, hence obj*maxcls > 0.8 => obj > 0.8.
__global__ void __launch_bounds__(SCORE_THREADS) score_kernel(const float* __restrict__ preds) {
    const int b     = blockIdx.x / BPB;
    const int chunk = blockIdx.x - b * BPB;
    const int wid   = threadIdx.x >> 5;
    const int lane  = threadIdx.x & 31;
    const int nbase = chunk * APB + wid * APW;

    const float* pb = preds + (size_t)b * NN * PSTR;

    // both obj groups loaded up front (2 loads in flight)
    float obj0 = __ldg(pb + (size_t)(nbase + lane) * PSTR + 4);
    float obj1 = (lane < 31) ? __ldg(pb + (size_t)(nbase + 32 + lane) * PSTR + 4) : 0.0f;
    unsigned b0m = __ballot_sync(0xFFFFFFFFu, obj0 > CONF_THRES);
    unsigned b1m = __ballot_sync(0xFFFFFFFFu, obj1 > CONF_THRES);
    unsigned long long ball = (unsigned long long)b0m
                            | ((unsigned long long)b1m << 32);   // bit k = anchor nbase+k

    if (!ball) return;

    // --- software pipeline: prefetch candidate k+1's rows while reducing k ---
    int k = __ffsll(ball) - 1;
    ball &= ball - 1;
    float o = (k < 32) ? __shfl_sync(0xFFFFFFFFu, obj0, k)
                       : __shfl_sync(0xFFFFFFFFu, obj1, k - 32);
    const float* p = pb + (size_t)(nbase + k) * PSTR;
    unsigned u0 = __float_as_uint(__ldg(p + 5 + lane));
    unsigned u1 = __float_as_uint(__ldg(p + 37 + lane));
    unsigned u2 = (lane < 16) ? __float_as_uint(__ldg(p + 69 + lane)) : 0u;

    while (true) {
        // prefetch next candidate
        int kn = -1;
        float on = 0.0f;
        unsigned v0 = 0u, v1 = 0u, v2 = 0u;
        if (ball) {
            kn = __ffsll(ball) - 1;
            ball &= ball - 1;
            on = (kn < 32) ? __shfl_sync(0xFFFFFFFFu, obj0, kn)
                           : __shfl_sync(0xFFFFFFFFu, obj1, kn - 32);
            const float* pn = pb + (size_t)(nbase + kn) * PSTR;
            v0 = __float_as_uint(__ldg(pn + 5 + lane));
            v1 = __float_as_uint(__ldg(pn + 37 + lane));
            v2 = (lane < 16) ? __float_as_uint(__ldg(pn + 69 + lane)) : 0u;
        }

        // process current candidate k
        {
            unsigned m3 = max(u0, max(u1, u2));
            // conservative pre-filter: emit requires maxcls > 0.8/o (margin >> ulp err)
            float thr = 0.8f / o - 1e-6f;
            if (__ballot_sync(0xFFFFFFFFu, __uint_as_float(m3) > thr)) {
                unsigned mx = __reduce_max_sync(0xFFFFFFFFu, m3);
                float sc = o * __uint_as_float(mx);     // exact reference arithmetic
                if (sc > CONF_THRES) {
                    unsigned cand = 0xFFFFu;
                    if (u2 == mx) cand = lane + 64;
                    if (u1 == mx) cand = lane + 32;
                    if (u0 == mx) cand = lane;          // lowest class index wins ties
                    unsigned cl = __reduce_min_sync(0xFFFFFFFFu, cand);
                    if (lane == 0) {
                        int na = nbase + k;
                        int bin = score_bin(sc);
                        int pos = atomicAdd(&g_hist[b][bin], 1);
                        if (pos < SLOTS) {
                            g_bin[b][bin][pos] =
                                ((unsigned long long)__float_as_uint(sc) << 32)
                              | ((unsigned long long)(((unsigned)na ^ 0xFFFFu)) << 16)
                              | (unsigned long long)cl;
                        }
                    }
                }
            }
        }

        if (kn < 0) break;
        k = kn; o = on; u0 = v0; u1 = v1; u2 = v2;
    }
}

// ============ Kernel B: top-300 + NMS + outputs, one block per batch ============
__global__ void __launch_bounds__(1024) post_kernel(
    const float* __restrict__ preds,
    const float* __restrict__ tgt,
    const int*   __restrict__ tlen,
    float* __restrict__ out)
{
    __shared__ int      s_S[NBINS + 1];     // suffix sums; s_S[NBINS] = 0
    __shared__ int      s_w[16];
    __shared__ unsigned long long s_key[SURV_MAX];
    __shared__ float    t_score[MAX_DET];
    __shared__ int      t_anchor[MAX_DET];
    __shared__ int      t_label[MAX_DET];
    __shared__ float4   t_box[MAX_DET];
    __shared__ float    t_area[MAX_DET];
    __shared__ __align__(16) unsigned s_mask[MAX_DET][KWPAD];
    __shared__ unsigned s_lbl[NCLS][KW];
    __shared__ unsigned s_nz[KW];
    __shared__ unsigned s_keepw[KW];
    __shared__ int      s_cutoff;

    const int b    = blockIdx.x;
    const int tid  = threadIdx.x;
    const int nt   = blockDim.x;   // 1024
    const int lane = tid & 31;
    const int wrp  = tid >> 5;     // 0..31

    const int OFF_PB = 0;
    const int OFF_PS = BB * MAX_DET * 4;           // 19200
    const int OFF_PL = OFF_PS + BB * MAX_DET;      // 24000
    const int OFF_PV = OFF_PL + BB * MAX_DET;      // 28800
    const int OFF_TB = OFF_PV + BB * MAX_DET;      // 33600
    const int OFF_TS = OFF_TB + BB * M_TGT * 4;    // 36800
    const int OFF_TL = OFF_TS + BB * M_TGT;        // 37600
    const int OFF_TV = OFF_TL + BB * M_TGT;        // 38400

    // ---- load reversed counts, re-zero SAME address (race-free), shuffle-scan ----
    int v = 0;
    if (tid < NBINS) {
        v = g_hist[b][NBINS - 1 - tid];    // reversed: prefix over rev == suffix
        g_hist[b][NBINS - 1 - tid] = 0;    // zero what THIS thread read (no race)
        if (v > SLOTS) v = SLOTS;          // clamp to stored items
    }
    if (tid == 0) { s_cutoff = 0; s_S[NBINS] = 0; }
    // warp-inclusive prefix scan (warps 0..15 hold data)
    #pragma unroll
    for (int off = 1; off < 32; off <<= 1) {
        int u = __shfl_up_sync(0xFFFFFFFFu, v, off);
        if (lane >= off) v += u;
    }
    if (tid < NBINS && lane == 31) s_w[wrp] = v;
    __syncthreads();
    if (tid < 16) {
        int w = s_w[tid];
        #pragma unroll
        for (int off = 1; off < 16; off <<= 1) {
            int u = __shfl_up_sync(0xFFFFu, w, off);
            if (tid >= off) w += u;
        }
        s_w[tid] = w;
    }
    __syncthreads();
    if (tid < NBINS) {
        int total = v + (wrp > 0 ? s_w[wrp - 1] : 0);
        s_S[NBINS - 1 - tid] = total;
    }
    __syncthreads();

    // cutoff: largest bin with suffix >= MAX_DET (0 if total < MAX_DET)
    if (tid < NBINS) {
        if (s_S[tid] >= MAX_DET && (tid == NBINS - 1 || s_S[tid + 1] < MAX_DET)) s_cutoff = tid;
    }
    // zero-init t arrays + lbl maps while waiting
    for (int i = tid; i < MAX_DET; i += nt) { t_score[i] = 0.0f; t_anchor[i] = 0; t_label[i] = 0; }
    for (int i = tid; i < NCLS * KW; i += nt) ((unsigned*)s_lbl)[i] = 0u;
    __syncthreads();
    const int cutoff = s_cutoff;
    const int S = s_S[cutoff];                       // <= 300 + SLOTS
    const int nval = (S < MAX_DET) ? S : MAX_DET;

    // copy surviving bins into s_key: warp per bin, lane-parallel slots
    for (int bin = cutoff + wrp; bin < NBINS; bin += 32) {
        int base = s_S[bin + 1];
        int cnt  = s_S[bin] - base;
        if (lane < cnt)      s_key[base + lane]      = g_bin[b][bin][lane];
        if (lane + 32 < cnt) s_key[base + lane + 32] = g_bin[b][bin][lane + 32];
    }
    __syncthreads();

    // bin-local exact rank: r = (#items in higher bins) + rank within bin group
    for (int i = tid; i < S; i += nt) {
        unsigned long long k = s_key[i];
        float sc = __uint_as_float((unsigned)(k >> 32));
        int bin = score_bin(sc);
        int base = s_S[bin + 1], end = s_S[bin];
        int r = base;
        for (int j = base; j < end; j++) r += (s_key[j] > k);
        if (r < MAX_DET) {
            t_score[r]  = sc;
            t_anchor[r] = (int)((~(unsigned)(k >> 16)) & 0xFFFFu);
            t_label[r]  = (int)(k & 0xFFFFu);
        }
    }
    __syncthreads();

    // gather boxes (cxcywh -> xyxy with x2=x1+w, ref bit-exact); zero mask pad
    for (int i = tid; i < MAX_DET; i += nt) {
        float4 bx = make_float4(0.f, 0.f, 0.f, 0.f);
        float ar = 0.f;
        if (i < nval) {
            const float* p = preds + ((size_t)b * NN + t_anchor[i]) * PSTR;
            float cx = __ldg(p), cy = __ldg(p + 1), w = __ldg(p + 2), h = __ldg(p + 3);
            float x1 = cx - 0.5f * w;
            float y1 = cy - 0.5f * h;
            float x2 = x1 + w;
            float y2 = y1 + h;
            bx = make_float4(x1, y1, x2, y2);
            ar = fmaxf(x2 - x1, 0.0f) * fmaxf(y2 - y1, 0.0f);
        }
        t_box[i]  = bx;
        t_area[i] = ar;
        s_mask[i][KW]     = 0u;
        s_mask[i][KW + 1] = 0u;
    }

    // targets (independent)
    int L = tlen[b];
    for (int m = tid; m < M_TGT; m += nt) {
        const float* q = tgt + ((size_t)b * M_TGT + m) * 6;
        bool vv = (m < L);
        float cx = q[0], cy = q[1], w = q[2], h = q[3], sc = q[4], lb = q[5];
        float x1 = cx - 0.5f * w;
        float y1 = cy - 0.5f * h;
        float* tb = out + OFF_TB + ((size_t)b * M_TGT + m) * 4;
        tb[0] = vv ? x1 : 0.0f;
        tb[1] = vv ? y1 : 0.0f;
        tb[2] = vv ? (x1 + w) : 0.0f;
        tb[3] = vv ? (y1 + h) : 0.0f;
        out[OFF_TS + b * M_TGT + m] = vv ? sc : 0.0f;
        out[OFF_TL + b * M_TGT + m] = vv ? lb : -1.0f;
        out[OFF_TV + b * M_TGT + m] = vv ? 1.0f : 0.0f;
    }
    __syncthreads();

    // label occupancy bitmaps
    for (int i = tid; i < nval; i += nt)
        atomicOr(&s_lbl[t_label[i]][i >> 5], 1u << (i & 31));
    __syncthreads();

    // suppression masks: only same-label j>i bits are examined
    for (int t = tid; t < KW * MAX_DET; t += nt) {
        int w = t / MAX_DET;
        int i = t - w * MAX_DET;
        unsigned m = 0u;
        if (i < nval) {
            unsigned candw = s_lbl[t_label[i]][w];
            int iw = i >> 5;
            if (w < iw) candw = 0u;
            else if (w == iw) candw &= (0xFFFFFFFEu << (i & 31));   // bits j>i
            if (candw) {
                float4 bi = t_box[i];
                float  ai = t_area[i];
                int jbase = w << 5;
                do {
                    int k = __ffs(candw) - 1;
                    candw &= candw - 1;
                    int j = jbase + k;                 // j < nval by lblmap construction
                    float4 bj = t_box[j];
                    float  aj = t_area[j];
                    float xx1 = fmaxf(bi.x, bj.x);
                    float yy1 = fmaxf(bi.y, bj.y);
                    float xx2 = fminf(bi.z, bj.z);
                    float yy2 = fminf(bi.w, bj.w);
                    float inter = fmaxf(xx2 - xx1, 0.0f) * fmaxf(yy2 - yy1, 0.0f);
                    float iou = inter / ((ai + aj) - inter + 1e-9f);
                    if (iou > NMS_THRES) m |= (1u << k);
                } while (candw);
            }
        }
        s_mask[i][w] = m;
    }
    __syncthreads();

    // nonzero-row bitmap
    if (tid < 320) {
        int i = tid;
        bool nzb = false;
        if (i < MAX_DET) {
            uint4 m0 = *(const uint4*)&s_mask[i][0];
            uint4 m1 = *(const uint4*)&s_mask[i][4];
            uint4 m2 = *(const uint4*)&s_mask[i][8];
            nzb = (m0.x | m0.y | m0.z | m0.w | m1.x | m1.y | m1.z | m1.w | m2.x | m2.y) != 0u;
        }
        unsigned bal = __ballot_sync(0xFFFFFFFFu, nzb);
        if ((tid & 31) == 0) s_nz[tid >> 5] = bal;
    }
    __syncthreads();

    // greedy: visit only alive rows with nonzero masks (zero rows can't change rem)
    if (tid == 0) {
        unsigned rem[KW];
        for (int w = 0; w < KW; w++) rem[w] = 0u;
        for (int w = 0; w < KW; w++) {
            unsigned cand = s_nz[w] & ~rem[w];
            while (cand) {
                int k = __ffs(cand) - 1;
                cand &= cand - 1;
                if (!((rem[w] >> k) & 1u)) {
                    int i = (w << 5) + k;
                    uint4 m0 = *(const uint4*)&s_mask[i][0];
                    uint4 m1 = *(const uint4*)&s_mask[i][4];
                    uint4 m2 = *(const uint4*)&s_mask[i][8];
                    rem[0] |= m0.x; rem[1] |= m0.y; rem[2] |= m0.z; rem[3] |= m0.w;
                    rem[4] |= m1.x; rem[5] |= m1.y; rem[6] |= m1.z; rem[7] |= m1.w;
                    rem[8] |= m2.x; rem[9] |= m2.y;
                    cand &= ~rem[w];
                }
            }
        }
        for (int w = 0; w < KW; w++) s_keepw[w] = ~rem[w];
    }
    __syncthreads();

    // prediction outputs
    for (int i = tid; i < MAX_DET; i += nt) {
        bool kp = (i < nval) && ((s_keepw[i >> 5] >> (i & 31)) & 1u);
        float4 bx = kp ? t_box[i] : make_float4(0.f, 0.f, 0.f, 0.f);
        *(float4*)(out + OFF_PB + ((size_t)b * MAX_DET + i) * 4) = bx;
        out[OFF_PS + b * MAX_DET + i] = kp ? t_score[i] : 0.0f;
        out[OFF_PL + b * MAX_DET + i] = kp ? (float)t_label[i] : -1.0f;
        out[OFF_PV + b * MAX_DET + i] = kp ? 1.0f : 0.0f;
    }
}

extern "C" void kernel_launch(void* const* d_in, const int* in_sizes, int n_in,
                              void* d_out, int out_size) {
    const float* preds = (const float*)d_in[0];
    const float* tgt   = (const float*)d_in[1];
    const int*   tlen  = (const int*)d_in[2];
    float* out = (float*)d_out;

    score_kernel<<<BB * BPB, SCORE_THREADS>>>(preds);   // 800 blocks
    post_kernel<<<BB, 1024>>>(preds, tgt, tlen, out);
}